// round 15
// baseline (speedup 1.0000x reference)
#include <cuda_runtime.h>
#include <cuda_fp16.h>
#include <math.h>
#include <stdint.h>

#define BB   8
#define SS   512
#define HH   768
#define NHH  12
#define DHH  64
#define FFF  3072
#define MM   (BB * SS)
#define LN_EPS 1e-3f

// ---------------------------------------------------------------------------
// Scratch
// ---------------------------------------------------------------------------
__device__ __align__(16) __half g_xh  [MM * HH];
__device__ __align__(16) __half g_qkvh[MM * 3 * HH];
__device__ __align__(16) __half g_ctxh[MM * HH];
__device__ __align__(16) float g_t1a [MM * HH];
__device__ __align__(16) float g_t1b [MM * HH];
__device__ __align__(16) float g_h1 [MM * HH];
__device__ __align__(16) __half g_h1h[MM * HH];
__device__ __align__(16) __half g_ffh[MM * FFF];
__device__ __align__(16) float g_t2a [MM * HH];
__device__ __align__(16) float g_t2b [MM * HH];
__device__ __align__(16) __half g_wqkv[3 * HH * HH];
__device__ __align__(16) float g_bqkv[3 * HH];
__device__ __align__(16) __half g_wo [HH * HH];
__device__ __align__(16) __half g_w1 [FFF * HH];
__device__ __align__(16) __half g_w2 [HH * FFF];

// ---------------------------------------------------------------------------
// PTX wrappers
// ---------------------------------------------------------------------------
__device__ __forceinline__ uint32_t smem_u32(const void* p) {
    uint32_t a;
    asm("{ .reg .u64 t; cvta.to.shared.u64 t, %1; cvt.u32.u64 %0, t; }"
        : "=r"(a) : "l"(p));
    return a;
}
#define LDM4(R, ADDR) \
    asm volatile("ldmatrix.sync.aligned.m8n8.x4.shared.b16 {%0,%1,%2,%3}, [%4];" \
        : "=r"((R)[0]), "=r"((R)[1]), "=r"((R)[2]), "=r"((R)[3]) : "r"(ADDR))
#define LDM4T(R, ADDR) \
    asm volatile("ldmatrix.sync.aligned.m8n8.x4.trans.shared.b16 {%0,%1,%2,%3}, [%4];" \
        : "=r"((R)[0]), "=r"((R)[1]), "=r"((R)[2]), "=r"((R)[3]) : "r"(ADDR))
#define MMAF16(D, A, B0, B1) \
    asm volatile("mma.sync.aligned.m16n8k16.row.col.f32.f16.f16.f32 " \
        "{%0,%1,%2,%3}, {%4,%5,%6,%7}, {%8,%9}, {%0,%1,%2,%3};" \
        : "+f"((D)[0]), "+f"((D)[1]), "+f"((D)[2]), "+f"((D)[3]) \
        : "r"((A)[0]), "r"((A)[1]), "r"((A)[2]), "r"((A)[3]), "r"(B0), "r"(B1))
#define CP16(SADDR, GPTR) \
    asm volatile("cp.async.cg.shared.global [%0], [%1], 16;" \
        :: "r"(SADDR), "l"(GPTR))
#define CP_COMMIT() asm volatile("cp.async.commit_group;" ::: "memory")
#define CP_WAIT(N)  asm volatile("cp.async.wait_group %0;" :: "n"(N) : "memory")
#define EX2F16X2(R, A) \
    asm volatile("ex2.approx.f16x2 %0, %1;" : "=r"(R) : "r"(A))

__device__ __forceinline__ float gelu_f(float x) {
    return 0.5f * x * (1.0f + erff(x * 0.70710678118654752f));
}

// ---------------------------------------------------------------------------
// Fused prep kernel (unchanged)
// ---------------------------------------------------------------------------
#define PREP_BLOCKS 9985

__global__ void __launch_bounds__(256) prep_kernel(
    const float* __restrict__ Wq, const float* __restrict__ Wk,
    const float* __restrict__ Wv, const float* __restrict__ Wo,
    const float* __restrict__ W1, const float* __restrict__ W2,
    const float* __restrict__ x,
    const float* __restrict__ bq, const float* __restrict__ bk,
    const float* __restrict__ bv,
    __half* __restrict__ wqkv, __half* __restrict__ wo,
    __half* __restrict__ w1, __half* __restrict__ w2,
    __half* __restrict__ xh, float* __restrict__ bqkv)
{
    __shared__ float tile[32][33];
    const int id = blockIdx.x;
    const int t  = threadIdx.x;
    const int tx = t & 31, ty = t >> 5;

    const float* in = nullptr;
    __half* out = nullptr;
    int K = 0, N = 0, bx = 0, by = 0;

    if (id < 2304) {
        const int z = id / 576, within = id % 576;
        in  = (z == 0) ? Wq : (z == 1) ? Wk : (z == 2) ? Wv : Wo;
        out = (z < 3) ? (wqkv + z * HH * HH) : wo;
        K = HH; N = HH; bx = within % 24; by = within / 24;
    } else if (id < 4608) {
        const int within = id - 2304;
        in = W1; out = w1; K = HH; N = FFF;
        bx = within % 96; by = within / 96;
    } else if (id < 6912) {
        const int within = id - 4608;
        in = W2; out = w2; K = FFF; N = HH;
        bx = within % 24; by = within / 24;
    } else if (id < 9984) {
        const int i = (id - 6912) * 256 + t;
        const float4 v = *(const float4*)(x + (size_t)i * 4);
        __half2 h0 = __floats2half2_rn(v.x, v.y);
        __half2 h1 = __floats2half2_rn(v.z, v.w);
        uint2 u; u.x = *(uint32_t*)&h0; u.y = *(uint32_t*)&h1;
        *(uint2*)(xh + (size_t)i * 4) = u;
        return;
    } else {
        for (int i = t; i < HH; i += 256) {
            bqkv[i] = bq[i]; bqkv[HH + i] = bk[i]; bqkv[2 * HH + i] = bv[i];
        }
        return;
    }

    const int n0 = bx * 32, k0 = by * 32;
#pragma unroll
    for (int j = 0; j < 32; j += 8)
        tile[ty + j][tx] = in[(size_t)(k0 + ty + j) * N + n0 + tx];
    __syncthreads();
#pragma unroll
    for (int j = 0; j < 32; j += 8)
        out[(size_t)(n0 + ty + j) * K + k0 + tx] = __float2half_rn(tile[tx][ty + j]);
}

// ---------------------------------------------------------------------------
// GEMM: fp16, KC=64, 2-stage, 1 sync/chunk. BN=128, warp grid 2x4.
//   EPI 0: bias -> fp16; 1: bias+GELU -> fp16; 3: raw fp32 partial (split-K)
//   Kstride = full row stride; Kloop = this CTA's K extent;
//   koff = blockIdx.z * Kloop; partial z writes to C + z*MM*Ntot.
// ---------------------------------------------------------------------------
#define KC 64
#define ROWB 144
#define NSTAGE 2

template <int EPI, int MT>
__global__ void __launch_bounds__(256) tc_gemm(
    const __half* __restrict__ Ahi,
    const __half* __restrict__ Whi,
    const float* __restrict__ bias,
    float* __restrict__ C, __half* __restrict__ Chi,
    int Kstride, int Kloop, int Ntot)
{
    constexpr int BM = MT * 32;
    constexpr int AMATB = BM * ROWB;
    constexpr int BMATB = 128 * ROWB;
    constexpr int STAGEB = AMATB + BMATB;
    constexpr int ACH = BM * 8;
    constexpr int NCHK = (ACH + 1024) / 256;

    extern __shared__ char sm[];
    const uint32_t sb = smem_u32(sm);

    const int t    = threadIdx.x;
    const int wid  = t >> 5, lane = t & 31;
    const int wm   = wid >> 2;
    const int wn   = wid & 3;
    const int bn   = blockIdx.x, bm = blockIdx.y;
    const int rbase = bm * BM, cbase = bn * 128;
    const int koff = blockIdx.z * Kloop;
    const int nch  = Kloop / KC;

    auto issue = [&](int ci) {
        const int s = ci & 1;
        const uint32_t st = sb + s * STAGEB;
        const int kt = koff + ci * KC;
#pragma unroll
        for (int j = 0; j < NCHK; j++) {
            int id = t + j * 256;
            if (id < ACH) {
                const int r = id >> 3, c = id & 7;
                CP16(st + r * ROWB + c * 16,
                     Ahi + (size_t)(rbase + r) * Kstride + kt + c * 8);
            } else {
                id -= ACH;
                const int r = id >> 3, c = id & 7;
                CP16(st + AMATB + r * ROWB + c * 16,
                     Whi + (size_t)(cbase + r) * Kstride + kt + c * 8);
            }
        }
    };

    float acc[MT][4][4];
#pragma unroll
    for (int i = 0; i < MT; i++)
#pragma unroll
        for (int j = 0; j < 4; j++)
#pragma unroll
            for (int q = 0; q < 4; q++) acc[i][j][q] = 0.f;

    const uint32_t a_off = (uint32_t)((wm * (MT * 16) + (lane & 15)) * ROWB
                                      + ((lane >> 4) << 4));
    const uint32_t b_off = (uint32_t)((wn * 32 + ((lane & 7) | ((lane & 16) >> 1))) * ROWB
                                      + (((lane >> 3) & 1) << 4));

    issue(0); CP_COMMIT();

    for (int ci = 0; ci < nch; ci++) {
        CP_WAIT(0);
        __syncthreads();
        if (ci + 1 < nch) { issue(ci + 1); CP_COMMIT(); }

        const uint32_t sA  = sb + (ci & 1) * STAGEB;
        const uint32_t sBh = sA + AMATB;
#pragma unroll
        for (int ks = 0; ks < 4; ks++) {
            const uint32_t ko = ks * 32;
            uint32_t AH[MT][4], BH[2][4];
#pragma unroll
            for (int mt = 0; mt < MT; mt++)
                LDM4(AH[mt], sA + a_off + mt * (16 * ROWB) + ko);
#pragma unroll
            for (int n2 = 0; n2 < 2; n2++)
                LDM4(BH[n2], sBh + b_off + n2 * (16 * ROWB) + ko);
#pragma unroll
            for (int mt = 0; mt < MT; mt++) {
#pragma unroll
                for (int nt = 0; nt < 4; nt++) {
                    const uint32_t b0 = BH[nt >> 1][(nt & 1) * 2];
                    const uint32_t b1 = BH[nt >> 1][(nt & 1) * 2 + 1];
                    MMAF16(acc[mt][nt], AH[mt], b0, b1);
                }
            }
        }
    }

    float* Cz = C + (size_t)blockIdx.z * MM * Ntot;

    const int mrow0 = rbase + wm * (MT * 16) + (lane >> 2);
    const int ncol0 = cbase + wn * 32 + (lane & 3) * 2;
#pragma unroll
    for (int mt = 0; mt < MT; mt++) {
#pragma unroll
        for (int half = 0; half < 2; half++) {
            const int m = mrow0 + mt * 16 + half * 8;
            const size_t rowoff = (size_t)m * Ntot;
#pragma unroll
            for (int nt = 0; nt < 4; nt++) {
                const int n = ncol0 + nt * 8;
                float v0 = acc[mt][nt][half * 2 + 0];
                float v1 = acc[mt][nt][half * 2 + 1];
                if (EPI == 3) {
                    *(float2*)(Cz + rowoff + n) = make_float2(v0, v1);
                } else {
                    const float2 bv = *(const float2*)(bias + n);
                    v0 += bv.x; v1 += bv.y;
                    if (EPI == 1) { v0 = gelu_f(v0); v1 = gelu_f(v1); }
                    __half2 hh = __floats2half2_rn(v0, v1);
                    *(__half2*)(Chi + rowoff + n) = hh;
                }
            }
        }
    }
}

// ---------------------------------------------------------------------------
// Tensor-core flash attention (R14 design, unchanged): ex2.f16x2 softmax,
// ones-MMA row sums, 256 threads, Q tile 128, 3-stage KV.
// ---------------------------------------------------------------------------
#define AROWB 144
#define AQB   (128 * AROWB)
#define AKVB  (64 * AROWB)
#define ASM_MASK AQB
#define ASM_KV   (AQB + 2048)
#define ASTAGEB  (2 * AKVB)
#define ATT_SMEM (ASM_KV + 3 * ASTAGEB)
#define ONES2 0x3C003C00u
#define SCL_L2E 0.180336880f
#define L2E     1.44269504f

__global__ void __launch_bounds__(256) attn_kernel(
    const __half* __restrict__ QKVh,
    const int* __restrict__ mask,
    __half* __restrict__ Ch)
{
    extern __shared__ char sm[];
    const uint32_t sb = smem_u32(sm);

    const int qt = blockIdx.x;
    const int bh = blockIdx.y;
    const int b  = bh / NHH;
    const int h  = bh % NHH;
    const int t  = threadIdx.x;
    const int w  = t >> 5, lane = t & 31;

    const int ST = 3 * HH;
    const size_t rowbase = (size_t)b * SS;
    const int qcol = h * DHH, kcol = HH + h * DHH, vcol = 2 * HH + h * DHH;

    auto issueKV = [&](int kt, int s) {
        const uint32_t st = sb + ASM_KV + s * ASTAGEB;
#pragma unroll
        for (int j = 0; j < 4; j++) {
            const int idx = t + j * 256;
            const int mat = idx >> 9;
            const int rem = idx & 511;
            const int r = rem >> 3, c = rem & 7;
            const int col = mat ? vcol : kcol;
            const size_t g = (rowbase + kt * 64 + r) * ST + col + c * 8;
            CP16(st + mat * AKVB + r * AROWB + c * 16, QKVh + g);
        }
    };

#pragma unroll
    for (int j = 0; j < 4; j++) {
        const int idx = t + j * 256;
        const int r = idx >> 3, c = idx & 7;
        const size_t g = (rowbase + qt * 128 + r) * ST + qcol + c * 8;
        CP16(sb + r * AROWB + c * 16, QKVh + g);
    }
    {
        float* am = (float*)(sm + ASM_MASK);
#pragma unroll
        for (int j = 0; j < 2; j++) {
            const int i = t + j * 256;
            am[i] = (1.0f - (float)mask[b * SS + i]) * (-10000.0f * L2E);
        }
    }
    issueKV(0, 0); CP_COMMIT();
    issueKV(1, 1); CP_COMMIT();

    float lacc[4] = {0.f, 0.f, 0.f, 0.f};
    float oacc[8][4];
#pragma unroll
    for (int i = 0; i < 8; i++)
#pragma unroll
        for (int j = 0; j < 4; j++) oacc[i][j] = 0.f;

    const uint32_t a_off = (uint32_t)((w * 16 + (lane & 15)) * AROWB + ((lane >> 4) << 4));
    const uint32_t b_row = (uint32_t)(((lane & 7) | ((lane & 16) >> 1)) * AROWB
                                      + (((lane >> 3) & 1) << 4));
    const uint32_t v_row = (uint32_t)((lane & 15) * AROWB + ((lane >> 4) << 4));
    const float* am = (const float*)(sm + ASM_MASK);

    for (int kt = 0; kt < SS / 64; kt++) {
        if (kt + 1 < SS / 64) { CP_WAIT(1); } else { CP_WAIT(0); }
        __syncthreads();
        if (kt + 2 < SS / 64) { issueKV(kt + 2, (kt + 2) % 3); CP_COMMIT(); }

        const uint32_t sK = sb + ASM_KV + (kt % 3) * ASTAGEB;
        const uint32_t sV = sK + AKVB;

        float sacc[8][4];
#pragma unroll
        for (int i = 0; i < 8; i++)
#pragma unroll
            for (int j = 0; j < 4; j++) sacc[i][j] = 0.f;

#pragma unroll
        for (int ks = 0; ks < 4; ks++) {
            const uint32_t ko = ks * 32;
            uint32_t qh[4];
            LDM4(qh, sb + a_off + ko);
#pragma unroll
            for (int n2 = 0; n2 < 4; n2++) {
                uint32_t kh[4];
                LDM4(kh, sK + b_row + n2 * (16 * AROWB) + ko);
                MMAF16(sacc[n2 * 2],     qh, kh[0], kh[1]);
                MMAF16(sacc[n2 * 2 + 1], qh, kh[2], kh[3]);
            }
        }

        const int colbase = kt * 64 + (lane & 3) * 2;
        uint32_t pa[8], pb[8];
#pragma unroll
        for (int nt = 0; nt < 8; nt++) {
            const float a0 = am[colbase + nt * 8];
            const float a1 = am[colbase + nt * 8 + 1];
            const float t0 = fmaf(sacc[nt][0], SCL_L2E, a0);
            const float t1 = fmaf(sacc[nt][1], SCL_L2E, a1);
            const float t2 = fmaf(sacc[nt][2], SCL_L2E, a0);
            const float t3 = fmaf(sacc[nt][3], SCL_L2E, a1);
            __half2 hA = __floats2half2_rn(t0, t1);
            __half2 hB = __floats2half2_rn(t2, t3);
            EX2F16X2(pa[nt], *(uint32_t*)&hA);
            EX2F16X2(pb[nt], *(uint32_t*)&hB);
        }

#pragma unroll
        for (int ks = 0; ks < 4; ks++) {
            uint32_t ah[4];
            ah[0] = pa[2 * ks];
            ah[1] = pb[2 * ks];
            ah[2] = pa[2 * ks + 1];
            ah[3] = pb[2 * ks + 1];
            MMAF16(lacc, ah, ONES2, ONES2);
#pragma unroll
            for (int dp = 0; dp < 4; dp++) {
                uint32_t vh[4];
                LDM4T(vh, sV + ks * (16 * AROWB) + v_row + dp * 32);
                MMAF16(oacc[dp * 2],     ah, vh[0], vh[1]);
                MMAF16(oacc[dp * 2 + 1], ah, vh[2], vh[3]);
            }
        }
    }

    const float inv0 = 1.0f / lacc[0], inv1 = 1.0f / lacc[2];

    const size_t row0 = (size_t)(b * SS + qt * 128 + w * 16 + (lane >> 2));
    const size_t row1 = row0 + 8;
    const int ocol = h * DHH + (lane & 3) * 2;
#pragma unroll
    for (int nt = 0; nt < 8; nt++) {
        const int n = ocol + nt * 8;
        __half2 h0 = __floats2half2_rn(oacc[nt][0] * inv0, oacc[nt][1] * inv0);
        __half2 h1 = __floats2half2_rn(oacc[nt][2] * inv1, oacc[nt][3] * inv1);
        *(__half2*)(Ch + row0 * HH + n) = h0;
        *(__half2*)(Ch + row1 * HH + n) = h1;
    }
}

// ---------------------------------------------------------------------------
// LayerNorm with fused split-K combine: v = p0 + p1 + bias + resid, then LN.
// SPLITOUT: also emit fp16 copy.
// ---------------------------------------------------------------------------
template <int SPLITOUT>
__global__ void __launch_bounds__(256) ln_comb_kernel(
    const float* __restrict__ P0, const float* __restrict__ P1,
    const float* __restrict__ bias, const float* __restrict__ resid,
    const float* __restrict__ gg, const float* __restrict__ bb,
    float* __restrict__ Y, __half* __restrict__ Yh)
{
    const int row = blockIdx.x;
    const size_t ro = (size_t)row * HH;
    const int c = threadIdx.x;

    float v[3];
#pragma unroll
    for (int j = 0; j < 3; j++) {
        const int cc = c + j * 256;
        v[j] = P0[ro + cc] + P1[ro + cc] + bias[cc] + resid[ro + cc];
    }
    float s  = v[0] + v[1] + v[2];
    float s2 = v[0] * v[0] + v[1] * v[1] + v[2] * v[2];

    __shared__ float sa[8], sb2[8];
    __shared__ float stats[2];
    const int lane = threadIdx.x & 31, w = threadIdx.x >> 5;
#pragma unroll
    for (int o = 16; o > 0; o >>= 1) {
        s  += __shfl_down_sync(0xffffffffu, s, o);
        s2 += __shfl_down_sync(0xffffffffu, s2, o);
    }
    if (lane == 0) { sa[w] = s; sb2[w] = s2; }
    __syncthreads();
    if (threadIdx.x == 0) {
        float ts = 0.f, ts2 = 0.f;
#pragma unroll
        for (int i = 0; i < 8; i++) { ts += sa[i]; ts2 += sb2[i]; }
        const float mu  = ts * (1.0f / HH);
        const float var = ts2 * (1.0f / HH) - mu * mu;
        stats[0] = mu;
        stats[1] = rsqrtf(var + LN_EPS);
    }
    __syncthreads();
    const float mu = stats[0], rstd = stats[1];
#pragma unroll
    for (int j = 0; j < 3; j++) {
        const int cc = c + j * 256;
        const float y = (v[j] - mu) * rstd * gg[cc] + bb[cc];
        Y[ro + cc] = y;
        if (SPLITOUT) Yh[ro + cc] = __float2half_rn(y);
    }
}

// ---------------------------------------------------------------------------
// Launch
// ---------------------------------------------------------------------------
extern "C" void kernel_launch(void* const* d_in, const int* in_sizes, int n_in,
                              void* d_out, int out_size)
{
    (void)in_sizes; (void)n_in; (void)out_size;
    const float* x    = (const float*)d_in[0];
    const int*   mask = (const int*)  d_in[1];
    const float* Wq   = (const float*)d_in[2];
    const float* bq   = (const float*)d_in[3];
    const float* Wk   = (const float*)d_in[4];
    const float* bk   = (const float*)d_in[5];
    const float* Wv   = (const float*)d_in[6];
    const float* bv   = (const float*)d_in[7];
    const float* Wo   = (const float*)d_in[8];
    const float* bo   = (const float*)d_in[9];
    const float* ln1g = (const float*)d_in[10];
    const float* ln1b = (const float*)d_in[11];
    const float* W1   = (const float*)d_in[12];
    const float* b1   = (const float*)d_in[13];
    const float* W2   = (const float*)d_in[14];
    const float* b2   = (const float*)d_in[15];
    const float* ln2g = (const float*)d_in[16];
    const float* ln2b = (const float*)d_in[17];
    float* out = (float*)d_out;

    __half *xh, *qkvh, *ctxh, *h1h, *ffh;
    __half *wqkv, *wo, *w1, *w2;
    float *t1a, *t1b, *h1, *t2a, *t2b, *bqkv;
    cudaGetSymbolAddress((void**)&xh, g_xh);
    cudaGetSymbolAddress((void**)&qkvh, g_qkvh);
    cudaGetSymbolAddress((void**)&ctxh, g_ctxh);
    cudaGetSymbolAddress((void**)&h1h, g_h1h);
    cudaGetSymbolAddress((void**)&ffh, g_ffh);
    cudaGetSymbolAddress((void**)&wqkv, g_wqkv);
    cudaGetSymbolAddress((void**)&wo, g_wo);
    cudaGetSymbolAddress((void**)&w1, g_w1);
    cudaGetSymbolAddress((void**)&w2, g_w2);
    cudaGetSymbolAddress((void**)&t1a, g_t1a);
    cudaGetSymbolAddress((void**)&t1b, g_t1b);
    cudaGetSymbolAddress((void**)&h1, g_h1);
    cudaGetSymbolAddress((void**)&t2a, g_t2a);
    cudaGetSymbolAddress((void**)&t2b, g_t2b);
    cudaGetSymbolAddress((void**)&bqkv, g_bqkv);

    constexpr int SM128 = (128 + 128) * ROWB * NSTAGE;   // 73728
    constexpr int SM64  = (64 + 128) * ROWB * NSTAGE;    // 55296

    cudaFuncSetAttribute(attn_kernel,
                         cudaFuncAttributeMaxDynamicSharedMemorySize, ATT_SMEM);
    cudaFuncSetAttribute(tc_gemm<0, 4>,
                         cudaFuncAttributeMaxDynamicSharedMemorySize, SM128);
    cudaFuncSetAttribute(tc_gemm<1, 4>,
                         cudaFuncAttributeMaxDynamicSharedMemorySize, SM128);
    cudaFuncSetAttribute(tc_gemm<3, 2>,
                         cudaFuncAttributeMaxDynamicSharedMemorySize, SM64);

    prep_kernel<<<PREP_BLOCKS, 256>>>(Wq, Wk, Wv, Wo, W1, W2, x, bq, bk, bv,
                                      wqkv, wo, w1, w2, xh, bqkv);

    // fused QKV -> fp16
    tc_gemm<0, 4><<<dim3(3 * HH / 128, MM / 128), 256, SM128>>>(
        xh, wqkv, bqkv, nullptr, qkvh, HH, HH, 3 * HH);

    // attention -> ctx fp16
    attn_kernel<<<dim3(SS / 128, BB * NHH), 256, ATT_SMEM>>>(
        qkvh, mask, ctxh);

    // Wo split-K=2: partials t1a (z=0), t1b (z=1)
    tc_gemm<3, 2><<<dim3(HH / 128, MM / 64, 2), 256, SM64>>>(
        ctxh, wo, nullptr, t1a, nullptr, HH, HH / 2, HH);
    // h1 = LN(t1a + t1b + bo + x)
    ln_comb_kernel<1><<<MM, 256>>>(t1a, t1b, bo, x, ln1g, ln1b, h1, h1h);

    // ff = gelu(h1 @ W1 + b1) -> fp16
    tc_gemm<1, 4><<<dim3(FFF / 128, MM / 128), 256, SM128>>>(
        h1h, w1, b1, nullptr, ffh, HH, HH, FFF);

    // FF2 split-K=2: partials t2a (z=0), t2b (z=1)
    tc_gemm<3, 2><<<dim3(HH / 128, MM / 64, 2), 256, SM64>>>(
        ffh, w2, nullptr, t2a, nullptr, FFF, FFF / 2, HH);
    // out = LN(t2a + t2b + b2 + h1)
    ln_comb_kernel<0><<<MM, 256>>>(t2a, t2b, b2, h1, ln2g, ln2b, out, nullptr);
}

// round 16
// speedup vs baseline: 1.0193x; 1.0193x over previous
#include <cuda_runtime.h>
#include <cuda_fp16.h>
#include <math.h>
#include <stdint.h>

#define BB   8
#define SS   512
#define HH   768
#define NHH  12
#define DHH  64
#define FFF  3072
#define MM   (BB * SS)
#define LN_EPS 1e-3f

// ---------------------------------------------------------------------------
// Scratch (all intermediates fp16)
// ---------------------------------------------------------------------------
__device__ __align__(16) __half g_xh  [MM * HH];
__device__ __align__(16) __half g_qkvh[MM * 3 * HH];
__device__ __align__(16) __half g_ctxh[MM * HH];
__device__ __align__(16) __half g_t1h[MM * HH];
__device__ __align__(16) __half g_h1h[MM * HH];
__device__ __align__(16) __half g_ffh[MM * FFF];
__device__ __align__(16) __half g_t2h[MM * HH];
__device__ __align__(16) __half g_wqkv[3 * HH * HH];
__device__ __align__(16) float g_bqkv[3 * HH];
__device__ __align__(16) __half g_wo [HH * HH];
__device__ __align__(16) __half g_w1 [FFF * HH];
__device__ __align__(16) __half g_w2 [HH * FFF];

// ---------------------------------------------------------------------------
// PTX wrappers
// ---------------------------------------------------------------------------
__device__ __forceinline__ uint32_t smem_u32(const void* p) {
    uint32_t a;
    asm("{ .reg .u64 t; cvta.to.shared.u64 t, %1; cvt.u32.u64 %0, t; }"
        : "=r"(a) : "l"(p));
    return a;
}
#define LDM4(R, ADDR) \
    asm volatile("ldmatrix.sync.aligned.m8n8.x4.shared.b16 {%0,%1,%2,%3}, [%4];" \
        : "=r"((R)[0]), "=r"((R)[1]), "=r"((R)[2]), "=r"((R)[3]) : "r"(ADDR))
#define LDM4T(R, ADDR) \
    asm volatile("ldmatrix.sync.aligned.m8n8.x4.trans.shared.b16 {%0,%1,%2,%3}, [%4];" \
        : "=r"((R)[0]), "=r"((R)[1]), "=r"((R)[2]), "=r"((R)[3]) : "r"(ADDR))
#define MMAF16(D, A, B0, B1) \
    asm volatile("mma.sync.aligned.m16n8k16.row.col.f32.f16.f16.f32 " \
        "{%0,%1,%2,%3}, {%4,%5,%6,%7}, {%8,%9}, {%0,%1,%2,%3};" \
        : "+f"((D)[0]), "+f"((D)[1]), "+f"((D)[2]), "+f"((D)[3]) \
        : "r"((A)[0]), "r"((A)[1]), "r"((A)[2]), "r"((A)[3]), "r"(B0), "r"(B1))
#define CP16(SADDR, GPTR) \
    asm volatile("cp.async.cg.shared.global [%0], [%1], 16;" \
        :: "r"(SADDR), "l"(GPTR))
#define CP_COMMIT() asm volatile("cp.async.commit_group;" ::: "memory")
#define CP_WAIT(N)  asm volatile("cp.async.wait_group %0;" :: "n"(N) : "memory")
#define EX2F16X2(R, A) \
    asm volatile("ex2.approx.f16x2 %0, %1;" : "=r"(R) : "r"(A))

__device__ __forceinline__ float gelu_f(float x) {
    return 0.5f * x * (1.0f + erff(x * 0.70710678118654752f));
}

// ---------------------------------------------------------------------------
// Fused prep kernel (unchanged from R14)
// ---------------------------------------------------------------------------
#define PREP_BLOCKS 9985

__global__ void __launch_bounds__(256) prep_kernel(
    const float* __restrict__ Wq, const float* __restrict__ Wk,
    const float* __restrict__ Wv, const float* __restrict__ Wo,
    const float* __restrict__ W1, const float* __restrict__ W2,
    const float* __restrict__ x,
    const float* __restrict__ bq, const float* __restrict__ bk,
    const float* __restrict__ bv,
    __half* __restrict__ wqkv, __half* __restrict__ wo,
    __half* __restrict__ w1, __half* __restrict__ w2,
    __half* __restrict__ xh, float* __restrict__ bqkv)
{
    __shared__ float tile[32][33];
    const int id = blockIdx.x;
    const int t  = threadIdx.x;
    const int tx = t & 31, ty = t >> 5;

    const float* in = nullptr;
    __half* out = nullptr;
    int K = 0, N = 0, bx = 0, by = 0;

    if (id < 2304) {
        const int z = id / 576, within = id % 576;
        in  = (z == 0) ? Wq : (z == 1) ? Wk : (z == 2) ? Wv : Wo;
        out = (z < 3) ? (wqkv + z * HH * HH) : wo;
        K = HH; N = HH; bx = within % 24; by = within / 24;
    } else if (id < 4608) {
        const int within = id - 2304;
        in = W1; out = w1; K = HH; N = FFF;
        bx = within % 96; by = within / 96;
    } else if (id < 6912) {
        const int within = id - 4608;
        in = W2; out = w2; K = FFF; N = HH;
        bx = within % 24; by = within / 24;
    } else if (id < 9984) {
        const int i = (id - 6912) * 256 + t;
        const float4 v = *(const float4*)(x + (size_t)i * 4);
        __half2 h0 = __floats2half2_rn(v.x, v.y);
        __half2 h1 = __floats2half2_rn(v.z, v.w);
        uint2 u; u.x = *(uint32_t*)&h0; u.y = *(uint32_t*)&h1;
        *(uint2*)(xh + (size_t)i * 4) = u;
        return;
    } else {
        for (int i = t; i < HH; i += 256) {
            bqkv[i] = bq[i]; bqkv[HH + i] = bk[i]; bqkv[2 * HH + i] = bv[i];
        }
        return;
    }

    const int n0 = bx * 32, k0 = by * 32;
#pragma unroll
    for (int j = 0; j < 32; j += 8)
        tile[ty + j][tx] = in[(size_t)(k0 + ty + j) * N + n0 + tx];
    __syncthreads();
#pragma unroll
    for (int j = 0; j < 32; j += 8)
        out[(size_t)(n0 + ty + j) * K + k0 + tx] = __float2half_rn(tile[tx][ty + j]);
}

// ---------------------------------------------------------------------------
// GEMM (R12/R14 core): fp16, KC=64, 2-stage, 1 sync/chunk, BN=128.
//   EPI 0: bias -> fp16; 1: bias+GELU -> fp16; 2: bias + fp16 resid -> fp16
// ---------------------------------------------------------------------------
#define KC 64
#define ROWB 144
#define NSTAGE 2

template <int EPI, int MT>
__global__ void __launch_bounds__(256) tc_gemm(
    const __half* __restrict__ Ahi,
    const __half* __restrict__ Whi,
    const float* __restrict__ bias, const __half* __restrict__ residh,
    __half* __restrict__ Chi,
    int K, int Ntot)
{
    constexpr int BM = MT * 32;
    constexpr int AMATB = BM * ROWB;
    constexpr int BMATB = 128 * ROWB;
    constexpr int STAGEB = AMATB + BMATB;
    constexpr int ACH = BM * 8;
    constexpr int NCHK = (ACH + 1024) / 256;

    extern __shared__ char sm[];
    const uint32_t sb = smem_u32(sm);

    const int t    = threadIdx.x;
    const int wid  = t >> 5, lane = t & 31;
    const int wm   = wid >> 2;
    const int wn   = wid & 3;
    const int bn   = blockIdx.x, bm = blockIdx.y;
    const int rbase = bm * BM, cbase = bn * 128;
    const int nch  = K / KC;

    auto issue = [&](int ci) {
        const int s = ci & 1;
        const uint32_t st = sb + s * STAGEB;
        const int kt = ci * KC;
#pragma unroll
        for (int j = 0; j < NCHK; j++) {
            int id = t + j * 256;
            if (id < ACH) {
                const int r = id >> 3, c = id & 7;
                CP16(st + r * ROWB + c * 16,
                     Ahi + (size_t)(rbase + r) * K + kt + c * 8);
            } else {
                id -= ACH;
                const int r = id >> 3, c = id & 7;
                CP16(st + AMATB + r * ROWB + c * 16,
                     Whi + (size_t)(cbase + r) * K + kt + c * 8);
            }
        }
    };

    float acc[MT][4][4];
#pragma unroll
    for (int i = 0; i < MT; i++)
#pragma unroll
        for (int j = 0; j < 4; j++)
#pragma unroll
            for (int q = 0; q < 4; q++) acc[i][j][q] = 0.f;

    const uint32_t a_off = (uint32_t)((wm * (MT * 16) + (lane & 15)) * ROWB
                                      + ((lane >> 4) << 4));
    const uint32_t b_off = (uint32_t)((wn * 32 + ((lane & 7) | ((lane & 16) >> 1))) * ROWB
                                      + (((lane >> 3) & 1) << 4));

    issue(0); CP_COMMIT();

    for (int ci = 0; ci < nch; ci++) {
        CP_WAIT(0);
        __syncthreads();
        if (ci + 1 < nch) { issue(ci + 1); CP_COMMIT(); }

        const uint32_t sA  = sb + (ci & 1) * STAGEB;
        const uint32_t sBh = sA + AMATB;
#pragma unroll
        for (int ks = 0; ks < 4; ks++) {
            const uint32_t ko = ks * 32;
            uint32_t AH[MT][4], BH[2][4];
#pragma unroll
            for (int mt = 0; mt < MT; mt++)
                LDM4(AH[mt], sA + a_off + mt * (16 * ROWB) + ko);
#pragma unroll
            for (int n2 = 0; n2 < 2; n2++)
                LDM4(BH[n2], sBh + b_off + n2 * (16 * ROWB) + ko);
#pragma unroll
            for (int mt = 0; mt < MT; mt++) {
#pragma unroll
                for (int nt = 0; nt < 4; nt++) {
                    const uint32_t b0 = BH[nt >> 1][(nt & 1) * 2];
                    const uint32_t b1 = BH[nt >> 1][(nt & 1) * 2 + 1];
                    MMAF16(acc[mt][nt], AH[mt], b0, b1);
                }
            }
        }
    }

    const int mrow0 = rbase + wm * (MT * 16) + (lane >> 2);
    const int ncol0 = cbase + wn * 32 + (lane & 3) * 2;
#pragma unroll
    for (int mt = 0; mt < MT; mt++) {
#pragma unroll
        for (int half = 0; half < 2; half++) {
            const int m = mrow0 + mt * 16 + half * 8;
            const size_t rowoff = (size_t)m * Ntot;
#pragma unroll
            for (int nt = 0; nt < 4; nt++) {
                const int n = ncol0 + nt * 8;
                float v0 = acc[mt][nt][half * 2 + 0];
                float v1 = acc[mt][nt][half * 2 + 1];
                const float2 bv = *(const float2*)(bias + n);
                v0 += bv.x; v1 += bv.y;
                if (EPI == 2) {
                    const __half2 rv = *(const __half2*)(residh + rowoff + n);
                    const float2 rf = __half22float2(rv);
                    v0 += rf.x; v1 += rf.y;
                } else if (EPI == 1) {
                    v0 = gelu_f(v0); v1 = gelu_f(v1);
                }
                __half2 hh = __floats2half2_rn(v0, v1);
                *(__half2*)(Chi + rowoff + n) = hh;
            }
        }
    }
}

// ---------------------------------------------------------------------------
// Tensor-core flash attention (R14 design, unchanged): ex2.f16x2 softmax,
// ones-MMA row sums, 256 threads, Q tile 128, 3-stage KV.
// ---------------------------------------------------------------------------
#define AROWB 144
#define AQB   (128 * AROWB)
#define AKVB  (64 * AROWB)
#define ASM_MASK AQB
#define ASM_KV   (AQB + 2048)
#define ASTAGEB  (2 * AKVB)
#define ATT_SMEM (ASM_KV + 3 * ASTAGEB)
#define ONES2 0x3C003C00u
#define SCL_L2E 0.180336880f
#define L2E     1.44269504f

__global__ void __launch_bounds__(256) attn_kernel(
    const __half* __restrict__ QKVh,
    const int* __restrict__ mask,
    __half* __restrict__ Ch)
{
    extern __shared__ char sm[];
    const uint32_t sb = smem_u32(sm);

    const int qt = blockIdx.x;
    const int bh = blockIdx.y;
    const int b  = bh / NHH;
    const int h  = bh % NHH;
    const int t  = threadIdx.x;
    const int w  = t >> 5, lane = t & 31;

    const int ST = 3 * HH;
    const size_t rowbase = (size_t)b * SS;
    const int qcol = h * DHH, kcol = HH + h * DHH, vcol = 2 * HH + h * DHH;

    auto issueKV = [&](int kt, int s) {
        const uint32_t st = sb + ASM_KV + s * ASTAGEB;
#pragma unroll
        for (int j = 0; j < 4; j++) {
            const int idx = t + j * 256;
            const int mat = idx >> 9;
            const int rem = idx & 511;
            const int r = rem >> 3, c = rem & 7;
            const int col = mat ? vcol : kcol;
            const size_t g = (rowbase + kt * 64 + r) * ST + col + c * 8;
            CP16(st + mat * AKVB + r * AROWB + c * 16, QKVh + g);
        }
    };

#pragma unroll
    for (int j = 0; j < 4; j++) {
        const int idx = t + j * 256;
        const int r = idx >> 3, c = idx & 7;
        const size_t g = (rowbase + qt * 128 + r) * ST + qcol + c * 8;
        CP16(sb + r * AROWB + c * 16, QKVh + g);
    }
    {
        float* am = (float*)(sm + ASM_MASK);
#pragma unroll
        for (int j = 0; j < 2; j++) {
            const int i = t + j * 256;
            am[i] = (1.0f - (float)mask[b * SS + i]) * (-10000.0f * L2E);
        }
    }
    issueKV(0, 0); CP_COMMIT();
    issueKV(1, 1); CP_COMMIT();

    float lacc[4] = {0.f, 0.f, 0.f, 0.f};
    float oacc[8][4];
#pragma unroll
    for (int i = 0; i < 8; i++)
#pragma unroll
        for (int j = 0; j < 4; j++) oacc[i][j] = 0.f;

    const uint32_t a_off = (uint32_t)((w * 16 + (lane & 15)) * AROWB + ((lane >> 4) << 4));
    const uint32_t b_row = (uint32_t)(((lane & 7) | ((lane & 16) >> 1)) * AROWB
                                      + (((lane >> 3) & 1) << 4));
    const uint32_t v_row = (uint32_t)((lane & 15) * AROWB + ((lane >> 4) << 4));
    const float* am = (const float*)(sm + ASM_MASK);

    for (int kt = 0; kt < SS / 64; kt++) {
        if (kt + 1 < SS / 64) { CP_WAIT(1); } else { CP_WAIT(0); }
        __syncthreads();
        if (kt + 2 < SS / 64) { issueKV(kt + 2, (kt + 2) % 3); CP_COMMIT(); }

        const uint32_t sK = sb + ASM_KV + (kt % 3) * ASTAGEB;
        const uint32_t sV = sK + AKVB;

        float sacc[8][4];
#pragma unroll
        for (int i = 0; i < 8; i++)
#pragma unroll
            for (int j = 0; j < 4; j++) sacc[i][j] = 0.f;

#pragma unroll
        for (int ks = 0; ks < 4; ks++) {
            const uint32_t ko = ks * 32;
            uint32_t qh[4];
            LDM4(qh, sb + a_off + ko);
#pragma unroll
            for (int n2 = 0; n2 < 4; n2++) {
                uint32_t kh[4];
                LDM4(kh, sK + b_row + n2 * (16 * AROWB) + ko);
                MMAF16(sacc[n2 * 2],     qh, kh[0], kh[1]);
                MMAF16(sacc[n2 * 2 + 1], qh, kh[2], kh[3]);
            }
        }

        const int colbase = kt * 64 + (lane & 3) * 2;
        uint32_t pa[8], pb[8];
#pragma unroll
        for (int nt = 0; nt < 8; nt++) {
            const float a0 = am[colbase + nt * 8];
            const float a1 = am[colbase + nt * 8 + 1];
            const float t0 = fmaf(sacc[nt][0], SCL_L2E, a0);
            const float t1 = fmaf(sacc[nt][1], SCL_L2E, a1);
            const float t2 = fmaf(sacc[nt][2], SCL_L2E, a0);
            const float t3 = fmaf(sacc[nt][3], SCL_L2E, a1);
            __half2 hA = __floats2half2_rn(t0, t1);
            __half2 hB = __floats2half2_rn(t2, t3);
            EX2F16X2(pa[nt], *(uint32_t*)&hA);
            EX2F16X2(pb[nt], *(uint32_t*)&hB);
        }

#pragma unroll
        for (int ks = 0; ks < 4; ks++) {
            uint32_t ah[4];
            ah[0] = pa[2 * ks];
            ah[1] = pb[2 * ks];
            ah[2] = pa[2 * ks + 1];
            ah[3] = pb[2 * ks + 1];
            MMAF16(lacc, ah, ONES2, ONES2);
#pragma unroll
            for (int dp = 0; dp < 4; dp++) {
                uint32_t vh[4];
                LDM4T(vh, sV + ks * (16 * AROWB) + v_row + dp * 32);
                MMAF16(oacc[dp * 2],     ah, vh[0], vh[1]);
                MMAF16(oacc[dp * 2 + 1], ah, vh[2], vh[3]);
            }
        }
    }

    const float inv0 = 1.0f / lacc[0], inv1 = 1.0f / lacc[2];

    const size_t row0 = (size_t)(b * SS + qt * 128 + w * 16 + (lane >> 2));
    const size_t row1 = row0 + 8;
    const int ocol = h * DHH + (lane & 3) * 2;
#pragma unroll
    for (int nt = 0; nt < 8; nt++) {
        const int n = ocol + nt * 8;
        __half2 h0 = __floats2half2_rn(oacc[nt][0] * inv0, oacc[nt][1] * inv0);
        __half2 h1 = __floats2half2_rn(oacc[nt][2] * inv1, oacc[nt][3] * inv1);
        *(__half2*)(Ch + row0 * HH + n) = h0;
        *(__half2*)(Ch + row1 * HH + n) = h1;
    }
}

// ---------------------------------------------------------------------------
// Row-wise LayerNorm over fp16 input.
//   OUTF32=0: write fp16 Yh (mid-network);  OUTF32=1: write fp32 Y (final).
// ---------------------------------------------------------------------------
template <int OUTF32>
__global__ void __launch_bounds__(256) ln_kernel(
    const __half* __restrict__ X, const float* __restrict__ gg,
    const float* __restrict__ bb, float* __restrict__ Y,
    __half* __restrict__ Yh)
{
    const int row = blockIdx.x;
    const __half* x = X + (size_t)row * HH;
    const int c = threadIdx.x;

    const float v0 = __half2float(x[c]);
    const float v1 = __half2float(x[c + 256]);
    const float v2 = __half2float(x[c + 512]);
    float s  = v0 + v1 + v2;
    float s2 = v0 * v0 + v1 * v1 + v2 * v2;

    __shared__ float sa[8], sb2[8];
    __shared__ float stats[2];
    const int lane = threadIdx.x & 31, w = threadIdx.x >> 5;
#pragma unroll
    for (int o = 16; o > 0; o >>= 1) {
        s  += __shfl_down_sync(0xffffffffu, s, o);
        s2 += __shfl_down_sync(0xffffffffu, s2, o);
    }
    if (lane == 0) { sa[w] = s; sb2[w] = s2; }
    __syncthreads();
    if (threadIdx.x == 0) {
        float ts = 0.f, ts2 = 0.f;
#pragma unroll
        for (int i = 0; i < 8; i++) { ts += sa[i]; ts2 += sb2[i]; }
        const float mu  = ts * (1.0f / HH);
        const float var = ts2 * (1.0f / HH) - mu * mu;
        stats[0] = mu;
        stats[1] = rsqrtf(var + LN_EPS);
    }
    __syncthreads();
    const float mu = stats[0], rstd = stats[1];
    const size_t ro = (size_t)row * HH;
#pragma unroll
    for (int j = 0; j < 3; j++) {
        const int cc = c + j * 256;
        const float vv = (j == 0 ? v0 : (j == 1 ? v1 : v2));
        const float y = (vv - mu) * rstd * gg[cc] + bb[cc];
        if (OUTF32) Y[ro + cc] = y;
        else        Yh[ro + cc] = __float2half_rn(y);
    }
}

// ---------------------------------------------------------------------------
// Launch
// ---------------------------------------------------------------------------
extern "C" void kernel_launch(void* const* d_in, const int* in_sizes, int n_in,
                              void* d_out, int out_size)
{
    (void)in_sizes; (void)n_in; (void)out_size;
    const float* x    = (const float*)d_in[0];
    const int*   mask = (const int*)  d_in[1];
    const float* Wq   = (const float*)d_in[2];
    const float* bq   = (const float*)d_in[3];
    const float* Wk   = (const float*)d_in[4];
    const float* bk   = (const float*)d_in[5];
    const float* Wv   = (const float*)d_in[6];
    const float* bv   = (const float*)d_in[7];
    const float* Wo   = (const float*)d_in[8];
    const float* bo   = (const float*)d_in[9];
    const float* ln1g = (const float*)d_in[10];
    const float* ln1b = (const float*)d_in[11];
    const float* W1   = (const float*)d_in[12];
    const float* b1   = (const float*)d_in[13];
    const float* W2   = (const float*)d_in[14];
    const float* b2   = (const float*)d_in[15];
    const float* ln2g = (const float*)d_in[16];
    const float* ln2b = (const float*)d_in[17];
    float* out = (float*)d_out;

    __half *xh, *qkvh, *ctxh, *t1h, *h1h, *ffh, *t2h;
    __half *wqkv, *wo, *w1, *w2;
    float *bqkv;
    cudaGetSymbolAddress((void**)&xh, g_xh);
    cudaGetSymbolAddress((void**)&qkvh, g_qkvh);
    cudaGetSymbolAddress((void**)&ctxh, g_ctxh);
    cudaGetSymbolAddress((void**)&t1h, g_t1h);
    cudaGetSymbolAddress((void**)&h1h, g_h1h);
    cudaGetSymbolAddress((void**)&ffh, g_ffh);
    cudaGetSymbolAddress((void**)&t2h, g_t2h);
    cudaGetSymbolAddress((void**)&wqkv, g_wqkv);
    cudaGetSymbolAddress((void**)&wo, g_wo);
    cudaGetSymbolAddress((void**)&w1, g_w1);
    cudaGetSymbolAddress((void**)&w2, g_w2);
    cudaGetSymbolAddress((void**)&bqkv, g_bqkv);

    constexpr int SM128 = (128 + 128) * ROWB * NSTAGE;   // 73728
    constexpr int SM64  = (64 + 128) * ROWB * NSTAGE;    // 55296

    cudaFuncSetAttribute(attn_kernel,
                         cudaFuncAttributeMaxDynamicSharedMemorySize, ATT_SMEM);
    cudaFuncSetAttribute(tc_gemm<0, 4>,
                         cudaFuncAttributeMaxDynamicSharedMemorySize, SM128);
    cudaFuncSetAttribute(tc_gemm<1, 4>,
                         cudaFuncAttributeMaxDynamicSharedMemorySize, SM128);
    cudaFuncSetAttribute(tc_gemm<2, 2>,
                         cudaFuncAttributeMaxDynamicSharedMemorySize, SM64);

    prep_kernel<<<PREP_BLOCKS, 256>>>(Wq, Wk, Wv, Wo, W1, W2, x, bq, bk, bv,
                                      wqkv, wo, w1, w2, xh, bqkv);

    // fused QKV -> fp16
    tc_gemm<0, 4><<<dim3(3 * HH / 128, MM / 128), 256, SM128>>>(
        xh, wqkv, bqkv, nullptr, qkvh, HH, 3 * HH);

    // attention -> ctx fp16
    attn_kernel<<<dim3(SS / 128, BB * NHH), 256, ATT_SMEM>>>(
        qkvh, mask, ctxh);

    // t1 = ctx @ Wo + bo + x   (residual from fp16 xh; fp16 out)
    tc_gemm<2, 2><<<dim3(HH / 128, MM / 64), 256, SM64>>>(
        ctxh, wo, bo, xh, t1h, HH, HH);
    // h1 = LN(t1) -> fp16 only
    ln_kernel<0><<<MM, 256>>>(t1h, ln1g, ln1b, nullptr, h1h);

    // ff = gelu(h1 @ W1 + b1) -> fp16
    tc_gemm<1, 4><<<dim3(FFF / 128, MM / 128), 256, SM128>>>(
        h1h, w1, b1, nullptr, ffh, HH, FFF);

    // t2 = ff @ W2 + b2 + h1   (fp16 residual, fp16 out)
    tc_gemm<2, 2><<<dim3(HH / 128, MM / 64), 256, SM64>>>(
        ffh, w2, b2, h1h, t2h, FFF, HH);
    // out = LN(t2) -> fp32
    ln_kernel<1><<<MM, 256>>>(t2h, ln2g, ln2b, out, nullptr);
}

// round 17
// speedup vs baseline: 1.0578x; 1.0378x over previous
#include <cuda_runtime.h>
#include <cuda_fp16.h>
#include <math.h>
#include <stdint.h>

#define BB   8
#define SS   512
#define HH   768
#define NHH  12
#define DHH  64
#define FFF  3072
#define MM   (BB * SS)
#define LN_EPS 1e-3f

// ---------------------------------------------------------------------------
// Scratch (all intermediates fp16)
// ---------------------------------------------------------------------------
__device__ __align__(16) __half g_xh  [MM * HH];
__device__ __align__(16) __half g_qkvh[MM * 3 * HH];
__device__ __align__(16) __half g_ctxh[MM * HH];
__device__ __align__(16) __half g_t1h[MM * HH];
__device__ __align__(16) __half g_h1h[MM * HH];
__device__ __align__(16) __half g_ffh[MM * FFF];
__device__ __align__(16) __half g_t2h[MM * HH];
__device__ __align__(16) __half g_wqkv[3 * HH * HH];
__device__ __align__(16) float g_bqkv[3 * HH];
__device__ __align__(16) __half g_wo [HH * HH];
__device__ __align__(16) __half g_w1 [FFF * HH];
__device__ __align__(16) __half g_w2 [HH * FFF];

// ---------------------------------------------------------------------------
// PTX wrappers
// ---------------------------------------------------------------------------
__device__ __forceinline__ uint32_t smem_u32(const void* p) {
    uint32_t a;
    asm("{ .reg .u64 t; cvta.to.shared.u64 t, %1; cvt.u32.u64 %0, t; }"
        : "=r"(a) : "l"(p));
    return a;
}
#define LDM4(R, ADDR) \
    asm volatile("ldmatrix.sync.aligned.m8n8.x4.shared.b16 {%0,%1,%2,%3}, [%4];" \
        : "=r"((R)[0]), "=r"((R)[1]), "=r"((R)[2]), "=r"((R)[3]) : "r"(ADDR))
#define LDM4T(R, ADDR) \
    asm volatile("ldmatrix.sync.aligned.m8n8.x4.trans.shared.b16 {%0,%1,%2,%3}, [%4];" \
        : "=r"((R)[0]), "=r"((R)[1]), "=r"((R)[2]), "=r"((R)[3]) : "r"(ADDR))
#define MMAF16(D, A, B0, B1) \
    asm volatile("mma.sync.aligned.m16n8k16.row.col.f32.f16.f16.f32 " \
        "{%0,%1,%2,%3}, {%4,%5,%6,%7}, {%8,%9}, {%0,%1,%2,%3};" \
        : "+f"((D)[0]), "+f"((D)[1]), "+f"((D)[2]), "+f"((D)[3]) \
        : "r"((A)[0]), "r"((A)[1]), "r"((A)[2]), "r"((A)[3]), "r"(B0), "r"(B1))
// L1-enabled async copy (.ca): weight/KV tiles are re-read across CTAs on the
// same SM; keeping them L1-resident cuts stage-fill latency 234 -> ~32 cyc.
#define CP16(SADDR, GPTR) \
    asm volatile("cp.async.ca.shared.global [%0], [%1], 16;" \
        :: "r"(SADDR), "l"(GPTR))
#define CP_COMMIT() asm volatile("cp.async.commit_group;" ::: "memory")
#define CP_WAIT(N)  asm volatile("cp.async.wait_group %0;" :: "n"(N) : "memory")
#define EX2F16X2(R, A) \
    asm volatile("ex2.approx.f16x2 %0, %1;" : "=r"(R) : "r"(A))

__device__ __forceinline__ float gelu_f(float x) {
    return 0.5f * x * (1.0f + erff(x * 0.70710678118654752f));
}

// ---------------------------------------------------------------------------
// Fused prep kernel (unchanged)
// ---------------------------------------------------------------------------
#define PREP_BLOCKS 9985

__global__ void __launch_bounds__(256) prep_kernel(
    const float* __restrict__ Wq, const float* __restrict__ Wk,
    const float* __restrict__ Wv, const float* __restrict__ Wo,
    const float* __restrict__ W1, const float* __restrict__ W2,
    const float* __restrict__ x,
    const float* __restrict__ bq, const float* __restrict__ bk,
    const float* __restrict__ bv,
    __half* __restrict__ wqkv, __half* __restrict__ wo,
    __half* __restrict__ w1, __half* __restrict__ w2,
    __half* __restrict__ xh, float* __restrict__ bqkv)
{
    __shared__ float tile[32][33];
    const int id = blockIdx.x;
    const int t  = threadIdx.x;
    const int tx = t & 31, ty = t >> 5;

    const float* in = nullptr;
    __half* out = nullptr;
    int K = 0, N = 0, bx = 0, by = 0;

    if (id < 2304) {
        const int z = id / 576, within = id % 576;
        in  = (z == 0) ? Wq : (z == 1) ? Wk : (z == 2) ? Wv : Wo;
        out = (z < 3) ? (wqkv + z * HH * HH) : wo;
        K = HH; N = HH; bx = within % 24; by = within / 24;
    } else if (id < 4608) {
        const int within = id - 2304;
        in = W1; out = w1; K = HH; N = FFF;
        bx = within % 96; by = within / 96;
    } else if (id < 6912) {
        const int within = id - 4608;
        in = W2; out = w2; K = FFF; N = HH;
        bx = within % 24; by = within / 24;
    } else if (id < 9984) {
        const int i = (id - 6912) * 256 + t;
        const float4 v = *(const float4*)(x + (size_t)i * 4);
        __half2 h0 = __floats2half2_rn(v.x, v.y);
        __half2 h1 = __floats2half2_rn(v.z, v.w);
        uint2 u; u.x = *(uint32_t*)&h0; u.y = *(uint32_t*)&h1;
        *(uint2*)(xh + (size_t)i * 4) = u;
        return;
    } else {
        for (int i = t; i < HH; i += 256) {
            bqkv[i] = bq[i]; bqkv[HH + i] = bk[i]; bqkv[2 * HH + i] = bv[i];
        }
        return;
    }

    const int n0 = bx * 32, k0 = by * 32;
#pragma unroll
    for (int j = 0; j < 32; j += 8)
        tile[ty + j][tx] = in[(size_t)(k0 + ty + j) * N + n0 + tx];
    __syncthreads();
#pragma unroll
    for (int j = 0; j < 32; j += 8)
        out[(size_t)(n0 + ty + j) * K + k0 + tx] = __float2half_rn(tile[tx][ty + j]);
}

// ---------------------------------------------------------------------------
// GEMM (R16 core): fp16, KC=64, 2-stage, 1 sync/chunk, BN=128.
//   EPI 0: bias -> fp16; 1: bias+GELU -> fp16; 2: bias + fp16 resid -> fp16
// ---------------------------------------------------------------------------
#define KC 64
#define ROWB 144
#define NSTAGE 2

template <int EPI, int MT>
__global__ void __launch_bounds__(256) tc_gemm(
    const __half* __restrict__ Ahi,
    const __half* __restrict__ Whi,
    const float* __restrict__ bias, const __half* __restrict__ residh,
    __half* __restrict__ Chi,
    int K, int Ntot)
{
    constexpr int BM = MT * 32;
    constexpr int AMATB = BM * ROWB;
    constexpr int BMATB = 128 * ROWB;
    constexpr int STAGEB = AMATB + BMATB;
    constexpr int ACH = BM * 8;
    constexpr int NCHK = (ACH + 1024) / 256;

    extern __shared__ char sm[];
    const uint32_t sb = smem_u32(sm);

    const int t    = threadIdx.x;
    const int wid  = t >> 5, lane = t & 31;
    const int wm   = wid >> 2;
    const int wn   = wid & 3;
    const int bn   = blockIdx.x, bm = blockIdx.y;
    const int rbase = bm * BM, cbase = bn * 128;
    const int nch  = K / KC;

    auto issue = [&](int ci) {
        const int s = ci & 1;
        const uint32_t st = sb + s * STAGEB;
        const int kt = ci * KC;
#pragma unroll
        for (int j = 0; j < NCHK; j++) {
            int id = t + j * 256;
            if (id < ACH) {
                const int r = id >> 3, c = id & 7;
                CP16(st + r * ROWB + c * 16,
                     Ahi + (size_t)(rbase + r) * K + kt + c * 8);
            } else {
                id -= ACH;
                const int r = id >> 3, c = id & 7;
                CP16(st + AMATB + r * ROWB + c * 16,
                     Whi + (size_t)(cbase + r) * K + kt + c * 8);
            }
        }
    };

    float acc[MT][4][4];
#pragma unroll
    for (int i = 0; i < MT; i++)
#pragma unroll
        for (int j = 0; j < 4; j++)
#pragma unroll
            for (int q = 0; q < 4; q++) acc[i][j][q] = 0.f;

    const uint32_t a_off = (uint32_t)((wm * (MT * 16) + (lane & 15)) * ROWB
                                      + ((lane >> 4) << 4));
    const uint32_t b_off = (uint32_t)((wn * 32 + ((lane & 7) | ((lane & 16) >> 1))) * ROWB
                                      + (((lane >> 3) & 1) << 4));

    issue(0); CP_COMMIT();

    for (int ci = 0; ci < nch; ci++) {
        CP_WAIT(0);
        __syncthreads();
        if (ci + 1 < nch) { issue(ci + 1); CP_COMMIT(); }

        const uint32_t sA  = sb + (ci & 1) * STAGEB;
        const uint32_t sBh = sA + AMATB;
#pragma unroll
        for (int ks = 0; ks < 4; ks++) {
            const uint32_t ko = ks * 32;
            uint32_t AH[MT][4], BH[2][4];
#pragma unroll
            for (int mt = 0; mt < MT; mt++)
                LDM4(AH[mt], sA + a_off + mt * (16 * ROWB) + ko);
#pragma unroll
            for (int n2 = 0; n2 < 2; n2++)
                LDM4(BH[n2], sBh + b_off + n2 * (16 * ROWB) + ko);
#pragma unroll
            for (int mt = 0; mt < MT; mt++) {
#pragma unroll
                for (int nt = 0; nt < 4; nt++) {
                    const uint32_t b0 = BH[nt >> 1][(nt & 1) * 2];
                    const uint32_t b1 = BH[nt >> 1][(nt & 1) * 2 + 1];
                    MMAF16(acc[mt][nt], AH[mt], b0, b1);
                }
            }
        }
    }

    const int mrow0 = rbase + wm * (MT * 16) + (lane >> 2);
    const int ncol0 = cbase + wn * 32 + (lane & 3) * 2;
#pragma unroll
    for (int mt = 0; mt < MT; mt++) {
#pragma unroll
        for (int half = 0; half < 2; half++) {
            const int m = mrow0 + mt * 16 + half * 8;
            const size_t rowoff = (size_t)m * Ntot;
#pragma unroll
            for (int nt = 0; nt < 4; nt++) {
                const int n = ncol0 + nt * 8;
                float v0 = acc[mt][nt][half * 2 + 0];
                float v1 = acc[mt][nt][half * 2 + 1];
                const float2 bv = *(const float2*)(bias + n);
                v0 += bv.x; v1 += bv.y;
                if (EPI == 2) {
                    const __half2 rv = *(const __half2*)(residh + rowoff + n);
                    const float2 rf = __half22float2(rv);
                    v0 += rf.x; v1 += rf.y;
                } else if (EPI == 1) {
                    v0 = gelu_f(v0); v1 = gelu_f(v1);
                }
                __half2 hh = __floats2half2_rn(v0, v1);
                *(__half2*)(Chi + rowoff + n) = hh;
            }
        }
    }
}

// ---------------------------------------------------------------------------
// Tensor-core flash attention (R14 design): ex2.f16x2 softmax,
// ones-MMA row sums, 256 threads, Q tile 128, 3-stage KV.
// ---------------------------------------------------------------------------
#define AROWB 144
#define AQB   (128 * AROWB)
#define AKVB  (64 * AROWB)
#define ASM_MASK AQB
#define ASM_KV   (AQB + 2048)
#define ASTAGEB  (2 * AKVB)
#define ATT_SMEM (ASM_KV + 3 * ASTAGEB)
#define ONES2 0x3C003C00u
#define SCL_L2E 0.180336880f
#define L2E     1.44269504f

__global__ void __launch_bounds__(256) attn_kernel(
    const __half* __restrict__ QKVh,
    const int* __restrict__ mask,
    __half* __restrict__ Ch)
{
    extern __shared__ char sm[];
    const uint32_t sb = smem_u32(sm);

    const int qt = blockIdx.x;
    const int bh = blockIdx.y;
    const int b  = bh / NHH;
    const int h  = bh % NHH;
    const int t  = threadIdx.x;
    const int w  = t >> 5, lane = t & 31;

    const int ST = 3 * HH;
    const size_t rowbase = (size_t)b * SS;
    const int qcol = h * DHH, kcol = HH + h * DHH, vcol = 2 * HH + h * DHH;

    auto issueKV = [&](int kt, int s) {
        const uint32_t st = sb + ASM_KV + s * ASTAGEB;
#pragma unroll
        for (int j = 0; j < 4; j++) {
            const int idx = t + j * 256;
            const int mat = idx >> 9;
            const int rem = idx & 511;
            const int r = rem >> 3, c = rem & 7;
            const int col = mat ? vcol : kcol;
            const size_t g = (rowbase + kt * 64 + r) * ST + col + c * 8;
            CP16(st + mat * AKVB + r * AROWB + c * 16, QKVh + g);
        }
    };

#pragma unroll
    for (int j = 0; j < 4; j++) {
        const int idx = t + j * 256;
        const int r = idx >> 3, c = idx & 7;
        const size_t g = (rowbase + qt * 128 + r) * ST + qcol + c * 8;
        CP16(sb + r * AROWB + c * 16, QKVh + g);
    }
    {
        float* am = (float*)(sm + ASM_MASK);
#pragma unroll
        for (int j = 0; j < 2; j++) {
            const int i = t + j * 256;
            am[i] = (1.0f - (float)mask[b * SS + i]) * (-10000.0f * L2E);
        }
    }
    issueKV(0, 0); CP_COMMIT();
    issueKV(1, 1); CP_COMMIT();

    float lacc[4] = {0.f, 0.f, 0.f, 0.f};
    float oacc[8][4];
#pragma unroll
    for (int i = 0; i < 8; i++)
#pragma unroll
        for (int j = 0; j < 4; j++) oacc[i][j] = 0.f;

    const uint32_t a_off = (uint32_t)((w * 16 + (lane & 15)) * AROWB + ((lane >> 4) << 4));
    const uint32_t b_row = (uint32_t)(((lane & 7) | ((lane & 16) >> 1)) * AROWB
                                      + (((lane >> 3) & 1) << 4));
    const uint32_t v_row = (uint32_t)((lane & 15) * AROWB + ((lane >> 4) << 4));
    const float* am = (const float*)(sm + ASM_MASK);

    for (int kt = 0; kt < SS / 64; kt++) {
        if (kt + 1 < SS / 64) { CP_WAIT(1); } else { CP_WAIT(0); }
        __syncthreads();
        if (kt + 2 < SS / 64) { issueKV(kt + 2, (kt + 2) % 3); CP_COMMIT(); }

        const uint32_t sK = sb + ASM_KV + (kt % 3) * ASTAGEB;
        const uint32_t sV = sK + AKVB;

        float sacc[8][4];
#pragma unroll
        for (int i = 0; i < 8; i++)
#pragma unroll
            for (int j = 0; j < 4; j++) sacc[i][j] = 0.f;

#pragma unroll
        for (int ks = 0; ks < 4; ks++) {
            const uint32_t ko = ks * 32;
            uint32_t qh[4];
            LDM4(qh, sb + a_off + ko);
#pragma unroll
            for (int n2 = 0; n2 < 4; n2++) {
                uint32_t kh[4];
                LDM4(kh, sK + b_row + n2 * (16 * AROWB) + ko);
                MMAF16(sacc[n2 * 2],     qh, kh[0], kh[1]);
                MMAF16(sacc[n2 * 2 + 1], qh, kh[2], kh[3]);
            }
        }

        const int colbase = kt * 64 + (lane & 3) * 2;
        uint32_t pa[8], pb[8];
#pragma unroll
        for (int nt = 0; nt < 8; nt++) {
            const float a0 = am[colbase + nt * 8];
            const float a1 = am[colbase + nt * 8 + 1];
            const float t0 = fmaf(sacc[nt][0], SCL_L2E, a0);
            const float t1 = fmaf(sacc[nt][1], SCL_L2E, a1);
            const float t2 = fmaf(sacc[nt][2], SCL_L2E, a0);
            const float t3 = fmaf(sacc[nt][3], SCL_L2E, a1);
            __half2 hA = __floats2half2_rn(t0, t1);
            __half2 hB = __floats2half2_rn(t2, t3);
            EX2F16X2(pa[nt], *(uint32_t*)&hA);
            EX2F16X2(pb[nt], *(uint32_t*)&hB);
        }

#pragma unroll
        for (int ks = 0; ks < 4; ks++) {
            uint32_t ah[4];
            ah[0] = pa[2 * ks];
            ah[1] = pb[2 * ks];
            ah[2] = pa[2 * ks + 1];
            ah[3] = pb[2 * ks + 1];
            MMAF16(lacc, ah, ONES2, ONES2);
#pragma unroll
            for (int dp = 0; dp < 4; dp++) {
                uint32_t vh[4];
                LDM4T(vh, sV + ks * (16 * AROWB) + v_row + dp * 32);
                MMAF16(oacc[dp * 2],     ah, vh[0], vh[1]);
                MMAF16(oacc[dp * 2 + 1], ah, vh[2], vh[3]);
            }
        }
    }

    const float inv0 = 1.0f / lacc[0], inv1 = 1.0f / lacc[2];

    const size_t row0 = (size_t)(b * SS + qt * 128 + w * 16 + (lane >> 2));
    const size_t row1 = row0 + 8;
    const int ocol = h * DHH + (lane & 3) * 2;
#pragma unroll
    for (int nt = 0; nt < 8; nt++) {
        const int n = ocol + nt * 8;
        __half2 h0 = __floats2half2_rn(oacc[nt][0] * inv0, oacc[nt][1] * inv0);
        __half2 h1 = __floats2half2_rn(oacc[nt][2] * inv1, oacc[nt][3] * inv1);
        *(__half2*)(Ch + row0 * HH + n) = h0;
        *(__half2*)(Ch + row1 * HH + n) = h1;
    }
}

// ---------------------------------------------------------------------------
// Row-wise LayerNorm over fp16 input.
//   OUTF32=0: write fp16 Yh (mid-network);  OUTF32=1: write fp32 Y (final).
// ---------------------------------------------------------------------------
template <int OUTF32>
__global__ void __launch_bounds__(256) ln_kernel(
    const __half* __restrict__ X, const float* __restrict__ gg,
    const float* __restrict__ bb, float* __restrict__ Y,
    __half* __restrict__ Yh)
{
    const int row = blockIdx.x;
    const __half* x = X + (size_t)row * HH;
    const int c = threadIdx.x;

    const float v0 = __half2float(x[c]);
    const float v1 = __half2float(x[c + 256]);
    const float v2 = __half2float(x[c + 512]);
    float s  = v0 + v1 + v2;
    float s2 = v0 * v0 + v1 * v1 + v2 * v2;

    __shared__ float sa[8], sb2[8];
    __shared__ float stats[2];
    const int lane = threadIdx.x & 31, w = threadIdx.x >> 5;
#pragma unroll
    for (int o = 16; o > 0; o >>= 1) {
        s  += __shfl_down_sync(0xffffffffu, s, o);
        s2 += __shfl_down_sync(0xffffffffu, s2, o);
    }
    if (lane == 0) { sa[w] = s; sb2[w] = s2; }
    __syncthreads();
    if (threadIdx.x == 0) {
        float ts = 0.f, ts2 = 0.f;
#pragma unroll
        for (int i = 0; i < 8; i++) { ts += sa[i]; ts2 += sb2[i]; }
        const float mu  = ts * (1.0f / HH);
        const float var = ts2 * (1.0f / HH) - mu * mu;
        stats[0] = mu;
        stats[1] = rsqrtf(var + LN_EPS);
    }
    __syncthreads();
    const float mu = stats[0], rstd = stats[1];
    const size_t ro = (size_t)row * HH;
#pragma unroll
    for (int j = 0; j < 3; j++) {
        const int cc = c + j * 256;
        const float vv = (j == 0 ? v0 : (j == 1 ? v1 : v2));
        const float y = (vv - mu) * rstd * gg[cc] + bb[cc];
        if (OUTF32) Y[ro + cc] = y;
        else        Yh[ro + cc] = __float2half_rn(y);
    }
}

// ---------------------------------------------------------------------------
// Launch
// ---------------------------------------------------------------------------
extern "C" void kernel_launch(void* const* d_in, const int* in_sizes, int n_in,
                              void* d_out, int out_size)
{
    (void)in_sizes; (void)n_in; (void)out_size;
    const float* x    = (const float*)d_in[0];
    const int*   mask = (const int*)  d_in[1];
    const float* Wq   = (const float*)d_in[2];
    const float* bq   = (const float*)d_in[3];
    const float* Wk   = (const float*)d_in[4];
    const float* bk   = (const float*)d_in[5];
    const float* Wv   = (const float*)d_in[6];
    const float* bv   = (const float*)d_in[7];
    const float* Wo   = (const float*)d_in[8];
    const float* bo   = (const float*)d_in[9];
    const float* ln1g = (const float*)d_in[10];
    const float* ln1b = (const float*)d_in[11];
    const float* W1   = (const float*)d_in[12];
    const float* b1   = (const float*)d_in[13];
    const float* W2   = (const float*)d_in[14];
    const float* b2   = (const float*)d_in[15];
    const float* ln2g = (const float*)d_in[16];
    const float* ln2b = (const float*)d_in[17];
    float* out = (float*)d_out;

    __half *xh, *qkvh, *ctxh, *t1h, *h1h, *ffh, *t2h;
    __half *wqkv, *wo, *w1, *w2;
    float *bqkv;
    cudaGetSymbolAddress((void**)&xh, g_xh);
    cudaGetSymbolAddress((void**)&qkvh, g_qkvh);
    cudaGetSymbolAddress((void**)&ctxh, g_ctxh);
    cudaGetSymbolAddress((void**)&t1h, g_t1h);
    cudaGetSymbolAddress((void**)&h1h, g_h1h);
    cudaGetSymbolAddress((void**)&ffh, g_ffh);
    cudaGetSymbolAddress((void**)&t2h, g_t2h);
    cudaGetSymbolAddress((void**)&wqkv, g_wqkv);
    cudaGetSymbolAddress((void**)&wo, g_wo);
    cudaGetSymbolAddress((void**)&w1, g_w1);
    cudaGetSymbolAddress((void**)&w2, g_w2);
    cudaGetSymbolAddress((void**)&bqkv, g_bqkv);

    constexpr int SM128 = (128 + 128) * ROWB * NSTAGE;   // 73728
    constexpr int SM64  = (64 + 128) * ROWB * NSTAGE;    // 55296

    cudaFuncSetAttribute(attn_kernel,
                         cudaFuncAttributeMaxDynamicSharedMemorySize, ATT_SMEM);
    cudaFuncSetAttribute(tc_gemm<0, 4>,
                         cudaFuncAttributeMaxDynamicSharedMemorySize, SM128);
    cudaFuncSetAttribute(tc_gemm<1, 4>,
                         cudaFuncAttributeMaxDynamicSharedMemorySize, SM128);
    cudaFuncSetAttribute(tc_gemm<2, 2>,
                         cudaFuncAttributeMaxDynamicSharedMemorySize, SM64);

    prep_kernel<<<PREP_BLOCKS, 256>>>(Wq, Wk, Wv, Wo, W1, W2, x, bq, bk, bv,
                                      wqkv, wo, w1, w2, xh, bqkv);

    // fused QKV -> fp16
    tc_gemm<0, 4><<<dim3(3 * HH / 128, MM / 128), 256, SM128>>>(
        xh, wqkv, bqkv, nullptr, qkvh, HH, 3 * HH);

    // attention -> ctx fp16
    attn_kernel<<<dim3(SS / 128, BB * NHH), 256, ATT_SMEM>>>(
        qkvh, mask, ctxh);

    // t1 = ctx @ Wo + bo + x   (fp16 residual, fp16 out)
    tc_gemm<2, 2><<<dim3(HH / 128, MM / 64), 256, SM64>>>(
        ctxh, wo, bo, xh, t1h, HH, HH);
    ln_kernel<0><<<MM, 256>>>(t1h, ln1g, ln1b, nullptr, h1h);

    // ff = gelu(h1 @ W1 + b1) -> fp16
    tc_gemm<1, 4><<<dim3(FFF / 128, MM / 128), 256, SM128>>>(
        h1h, w1, b1, nullptr, ffh, HH, FFF);

    // t2 = ff @ W2 + b2 + h1   (fp16 residual, fp16 out)
    tc_gemm<2, 2><<<dim3(HH / 128, MM / 64), 256, SM64>>>(
        ffh, w2, b2, h1h, t2h, FFF, HH);
    ln_kernel<1><<<MM, 256>>>(t2h, ln2g, ln2b, out, nullptr);
}